// round 5
// baseline (speedup 1.0000x reference)
#include <cuda_runtime.h>
#include <math.h>

#define NN 50000
#define EE 800000
#define IN_DIM 200
#define HD 128
#define DD 127
#define GG 512
#define EPSF 1e-5f

// ---------------- scratch (device globals; no allocation allowed) ----------------
__device__ float g_h[NN * HD];
__device__ float g_u[NN * HD];
__device__ float g_p[NN * HD];
__device__ float g_hl[NN * HD];
__device__ float g_m[NN * HD];
__device__ float g_wt[6 * HD * HD];
__device__ float g_wtin[IN_DIM * HD];
__device__ int   g_cnt[NN];        // histogram
__device__ int   g_rowptr[NN + 1]; // CSR row pointers
__device__ int   g_cur[NN];        // scatter cursors
__device__ int   g_dstidx[EE];     // CSR column (dst) indices

__device__ __forceinline__ float warp_sum(float v) {
#pragma unroll
    for (int o = 16; o; o >>= 1) v += __shfl_xor_sync(0xffffffffu, v, o);
    return v;
}

__device__ __forceinline__ void red_v4(float* p, float a, float b, float c, float d) {
    asm volatile("red.global.add.v4.f32 [%0], {%1,%2,%3,%4};"
                 :: "l"(p), "f"(a), "f"(b), "f"(c), "f"(d) : "memory");
}

// packed f32x2 FMA: acc.{lo,hi} += x.{lo,hi} * w.{lo,hi}
__device__ __forceinline__ void ffma2(unsigned long long& acc, unsigned long long x,
                                      unsigned long long w) {
    asm("fma.rn.f32x2 %0, %1, %2, %0;" : "+l"(acc) : "l"(x), "l"(w));
}

// ---------------- utility kernels ----------------
__global__ void zero4_kernel(float4* __restrict__ p, int n4) {
    int i = blockIdx.x * blockDim.x + threadIdx.x;
    if (i < n4) p[i] = make_float4(0.f, 0.f, 0.f, 0.f);
}

__global__ void zeroi_kernel(int* __restrict__ p, int n) {
    int i = blockIdx.x * blockDim.x + threadIdx.x;
    if (i < n) p[i] = 0;
}

__global__ void prep_weights(const float* __restrict__ att_w, const float* __restrict__ mlp_w) {
    int idx = blockIdx.x * blockDim.x + threadIdx.x;
    if (idx >= 6 * HD * HD) return;
    int w = idx >> 14;
    int k = (idx >> 7) & 127;
    int j = idx & 127;
    float val = 0.f;
    if (k < DD && j < DD) {
        const float* src = (w < 2) ? (att_w + w * DD * DD) : (mlp_w + (w - 2) * DD * DD);
        val = src[j * DD + k];
    }
    g_wt[idx] = val;
}

__global__ void prep_win(const float* __restrict__ w_in) {
    int idx = blockIdx.x * blockDim.x + threadIdx.x;
    if (idx >= IN_DIM * HD) return;
    int k = idx >> 7;
    int j = idx & 127;
    g_wtin[idx] = (j < DD) ? w_in[k * DD + j] : 0.f;
}

// ---------------- CSR build ----------------
__global__ void hist_kernel(const int* __restrict__ ei) {
    int e = blockIdx.x * blockDim.x + threadIdx.x;
    if (e < EE) atomicAdd(&g_cnt[ei[e]], 1);
}

__global__ void scan_kernel() {
    __shared__ int ssum[1024];
    int t = threadIdx.x;
    const int CH = (NN + 1023) / 1024;  // 49
    int base = t * CH;
    int s = 0;
    for (int i = 0; i < CH; i++) {
        int idx = base + i;
        if (idx < NN) s += g_cnt[idx];
    }
    ssum[t] = s;
    __syncthreads();
    // inclusive Hillis-Steele
    for (int d = 1; d < 1024; d <<= 1) {
        int v = (t >= d) ? ssum[t - d] : 0;
        __syncthreads();
        ssum[t] += v;
        __syncthreads();
    }
    int run = ssum[t] - s;  // exclusive offset for this chunk
    for (int i = 0; i < CH; i++) {
        int idx = base + i;
        if (idx < NN) {
            g_rowptr[idx] = run;
            g_cur[idx] = run;
            run += g_cnt[idx];
        }
    }
    if (t == 1023) g_rowptr[NN] = run;
}

__global__ void scatter_kernel(const int* __restrict__ ei) {
    int e = blockIdx.x * blockDim.x + threadIdx.x;
    if (e >= EE) return;
    int s = ei[e];
    int pos = atomicAdd(&g_cur[s], 1);
    g_dstidx[pos] = ei[EE + e];
}

// ---------------- GEMM: P[n][j] = sum_k U[n][k] * WT[k][j] (+ bias) ----------------
// 256 threads, TM=32 rows x 128 cols per block. Thread (cg,rg) computes 4 rows x 4 cols.
// x staged in smem DUPLICATED ({x,x} float2) so one LDS.64 broadcast yields a ready
// f32x2 operand; weights read as ulonglong2 (two aligned col-pairs per LDG.128).
// Inner loop is fma.rn.f32x2 (2 FMA/instr) — accumulation order identical to scalar version.
template <int K, bool HASBIAS>
__global__ void __launch_bounds__(256) gemm_kernel(const float* __restrict__ U,
                                                   const float* __restrict__ WT,
                                                   const float* __restrict__ bias,
                                                   float* __restrict__ P) {
    constexpr int TM = 32;
    constexpr int RPT = 4;
    constexpr int K4 = K / 4;
    extern __shared__ float2 xsd[];  // [K][TM] duplicated values
    int tid = threadIdx.x;
    int cg = tid & 31;   // cols 4*cg .. 4*cg+3
    int rg = tid >> 5;   // rows rg*4 .. rg*4+3
    int row0 = blockIdx.x * TM;

    // staging: idx = k4*TM + m  (lanes cover consecutive m -> conflict-free STS.64)
    for (int i = tid; i < K4 * TM; i += 256) {
        int k4 = i / TM, m = i - k4 * TM;
        int r = row0 + m;
        float4 xv = (r < NN) ? ((const float4*)(U + (size_t)r * K))[k4]
                             : make_float4(0.f, 0.f, 0.f, 0.f);
        xsd[(k4 * 4 + 0) * TM + m] = make_float2(xv.x, xv.x);
        xsd[(k4 * 4 + 1) * TM + m] = make_float2(xv.y, xv.y);
        xsd[(k4 * 4 + 2) * TM + m] = make_float2(xv.z, xv.z);
        xsd[(k4 * 4 + 3) * TM + m] = make_float2(xv.w, xv.w);
    }
    __syncthreads();

    unsigned long long acc[RPT][2];
#pragma unroll
    for (int r = 0; r < RPT; r++) { acc[r][0] = 0ull; acc[r][1] = 0ull; }

    const ulonglong2* W2 = (const ulonglong2*)WT;
    const unsigned long long* XS = (const unsigned long long*)xsd;
#pragma unroll 2
    for (int kq = 0; kq < K4; kq++) {
        ulonglong2 w0 = W2[(kq * 4 + 0) * 32 + cg];
        ulonglong2 w1 = W2[(kq * 4 + 1) * 32 + cg];
        ulonglong2 w2 = W2[(kq * 4 + 2) * 32 + cg];
        ulonglong2 w3 = W2[(kq * 4 + 3) * 32 + cg];
#pragma unroll
        for (int r = 0; r < RPT; r++) {
            int m = rg * RPT + r;
            unsigned long long x0 = XS[(kq * 4 + 0) * TM + m];
            unsigned long long x1 = XS[(kq * 4 + 1) * TM + m];
            unsigned long long x2 = XS[(kq * 4 + 2) * TM + m];
            unsigned long long x3 = XS[(kq * 4 + 3) * TM + m];
            ffma2(acc[r][0], x0, w0.x); ffma2(acc[r][1], x0, w0.y);
            ffma2(acc[r][0], x1, w1.x); ffma2(acc[r][1], x1, w1.y);
            ffma2(acc[r][0], x2, w2.x); ffma2(acc[r][1], x2, w2.y);
            ffma2(acc[r][0], x3, w3.x); ffma2(acc[r][1], x3, w3.y);
        }
    }

    float4 bv = make_float4(0.f, 0.f, 0.f, 0.f);
    if (HASBIAS) {
        int j0 = 4 * cg;
        bv.x = (j0 + 0 < DD) ? bias[j0 + 0] : 0.f;
        bv.y = (j0 + 1 < DD) ? bias[j0 + 1] : 0.f;
        bv.z = (j0 + 2 < DD) ? bias[j0 + 2] : 0.f;
        bv.w = (j0 + 3 < DD) ? bias[j0 + 3] : 0.f;
    }
#pragma unroll
    for (int r = 0; r < RPT; r++) {
        int gr = row0 + rg * RPT + r;
        if (gr < NN) {
            float2 p0 = *(float2*)&acc[r][0];
            float2 p1 = *(float2*)&acc[r][1];
            float4 res;
            res.x = p0.x + bv.x;
            res.y = p0.y + bv.y;
            res.z = p1.x + bv.z;
            res.w = (cg == 31) ? 0.f : p1.y + bv.w;  // col 127 is padding
            ((float4*)(P + (size_t)gr * HD))[cg] = res;
        }
    }
}

// ---------------- warp-per-node elementwise kernels ----------------

// out = proj(expmap0([0, P]))
__global__ void expmap_kernel(const float* __restrict__ P, float* __restrict__ out,
                              const float* __restrict__ cptr) {
    int warp = (blockIdx.x * blockDim.x + threadIdx.x) >> 5;
    int lane = threadIdx.x & 31;
    if (warp >= NN) return;
    float c = cptr[0], sc = sqrtf(c);
    float4 v = ((const float4*)(P + (size_t)warp * HD))[lane];
    float s = warp_sum(v.x * v.x + v.y * v.y + v.z * v.z + v.w * v.w);
    float n = fmaxf(sqrtf(s), 1e-9f);
    float sh = sc * sinhf(n / sc) / n;
    float wprev = __shfl_up_sync(0xffffffffu, v.w, 1);
    float4 o;
    o.x = (lane == 0) ? 0.f : sh * wprev;
    o.y = sh * v.x; o.z = sh * v.y; o.w = sh * v.z;
    float ss = warp_sum(((lane == 0) ? 0.f : o.x * o.x) + o.y * o.y + o.z * o.z + o.w * o.w);
    if (lane == 0) o.x = sqrtf(c + ss);
    ((float4*)(out + (size_t)warp * HD))[lane] = o;
}

// U = logmap0(H) spatial
__global__ void lognode_kernel(const float* __restrict__ H, float* __restrict__ U,
                               const float* __restrict__ cptr) {
    int warp = (blockIdx.x * blockDim.x + threadIdx.x) >> 5;
    int lane = threadIdx.x & 31;
    if (warp >= NN) return;
    float c = cptr[0], sc = sqrtf(c);
    float4 v = ((const float4*)(H + (size_t)warp * HD))[lane];
    float x0 = __shfl_sync(0xffffffffu, v.x, 0);
    float px = (lane == 0) ? 0.f : v.x * v.x;
    float s = warp_sum(px + v.y * v.y + v.z * v.z + v.w * v.w);
    float yn = fmaxf(sqrtf(s), 1e-9f);
    float d = sc * acoshf(fmaxf(x0 / sc, 1.f + EPSF));
    float a = d / yn;
    float nx = __shfl_down_sync(0xffffffffu, v.x, 1);
    float4 o;
    o.x = a * v.y; o.y = a * v.z; o.z = a * v.w;
    o.w = (lane == 31) ? 0.f : a * nx;
    ((float4*)(U + (size_t)warp * HD))[lane] = o;
}

// warp per SRC node over CSR: m[s] = sum_{e in row s} exp(-dist(hl[s],hl[d])) * h[d]
// register accumulation, plain store — no zeroing, no atomics.
__global__ void agg_kernel(const float* __restrict__ hl, const float* __restrict__ h,
                           float* __restrict__ m, const float* __restrict__ cptr) {
    int warp = (blockIdx.x * blockDim.x + threadIdx.x) >> 5;
    int lane = threadIdx.x & 31;
    if (warp >= NN) return;
    float c = cptr[0], sc = sqrtf(c);
    int beg = g_rowptr[warp], end = g_rowptr[warp + 1];
    float4 a = ((const float4*)(hl + (size_t)warp * HD))[lane];
    float4 acc = make_float4(0.f, 0.f, 0.f, 0.f);
    int d = (beg < end) ? g_dstidx[beg] : 0;
    for (int e = beg; e < end; e++) {
        int dn = (e + 1 < end) ? g_dstidx[e + 1] : 0;  // prefetch next index
        float4 b = ((const float4*)(hl + (size_t)d * HD))[lane];
        float4 hv = ((const float4*)(h + (size_t)d * HD))[lane];
        float p = ((lane == 0) ? -a.x * b.x : a.x * b.x) + a.y * b.y + a.z * b.z + a.w * b.w;
        p = warp_sum(p);
        float val = fmaxf(-p / c, 1.f + EPSF);
        float att = expf(-sc * acoshf(val));
        acc.x = fmaf(att, hv.x, acc.x);
        acc.y = fmaf(att, hv.y, acc.y);
        acc.z = fmaf(att, hv.z, acc.z);
        acc.w = fmaf(att, hv.w, acc.w);
        d = dn;
    }
    ((float4*)(m + (size_t)warp * HD))[lane] = acc;
}

// GIN combine
__global__ void combine_kernel(const float* __restrict__ Mv, float* __restrict__ H,
                               const float* __restrict__ cptr, const float* __restrict__ epsp,
                               int l) {
    int warp = (blockIdx.x * blockDim.x + threadIdx.x) >> 5;
    int lane = threadIdx.x & 31;
    if (warp >= NN) return;
    float c = cptr[0], sc = sqrtf(c), ep = epsp[l];
    float4 mv = ((const float4*)(Mv + (size_t)warp * HD))[lane];
    float4 hv = ((const float4*)(H + (size_t)warp * HD))[lane];
    float m0 = __shfl_sync(0xffffffffu, mv.x, 0);
    float pm = warp_sum(((lane == 0) ? 0.f : mv.x * mv.x) + mv.y * mv.y + mv.z * mv.z + mv.w * mv.w);
    float denom = sqrtf(fmaxf(m0 * m0 - pm, 1e-9f));
    float r = sc / denom;
    float ax = r * mv.x, ay = r * mv.y, az = r * mv.z, aw = r * mv.w;
    float ssum = warp_sum(((lane == 0) ? 0.f : ax * ax) + ay * ay + az * az + aw * aw);
    float t = sqrtf(c + ssum);
    float yn_a = fmaxf(sqrtf(ssum), 1e-9f);
    float d1 = sc * acoshf(fmaxf(t / sc, 1.f + EPSF));
    float cA = d1 / yn_a;
    float ph = warp_sum(((lane == 0) ? 0.f : hv.x * hv.x) + hv.y * hv.y + hv.z * hv.z + hv.w * hv.w);
    float hp0 = sqrtf(c + ph);
    float yn_h = fmaxf(sqrtf(ph), 1e-9f);
    float d2 = sc * acoshf(fmaxf(hp0 / sc, 1.f + EPSF));
    float cH = (1.f + ep) * d2 / yn_h;
    float4 vv;
    vv.x = (lane == 0) ? 0.f : cA * ax + cH * hv.x;
    vv.y = cA * ay + cH * hv.y;
    vv.z = cA * az + cH * hv.z;
    vv.w = cA * aw + cH * hv.w;
    float pv = warp_sum(vv.x * vv.x + vv.y * vv.y + vv.z * vv.z + vv.w * vv.w);
    float n = fmaxf(sqrtf(pv), 1e-9f);
    float sh = sc * sinhf(n / sc) / n;
    float4 o;
    o.x = (lane == 0) ? 0.f : sh * vv.x;
    o.y = sh * vv.y; o.z = sh * vv.z; o.w = sh * vv.w;
    float so = warp_sum(((lane == 0) ? 0.f : o.x * o.x) + o.y * o.y + o.z * o.z + o.w * o.w);
    if (lane == 0) o.x = sqrtf(c + so);
    ((float4*)(H + (size_t)warp * HD))[lane] = o;
}

// MLP epilogue: H = hyp_act(proj(expmap0([0,P])))
__global__ void mlp_epi_kernel(const float* __restrict__ P, float* __restrict__ H,
                               const float* __restrict__ cptr) {
    int warp = (blockIdx.x * blockDim.x + threadIdx.x) >> 5;
    int lane = threadIdx.x & 31;
    if (warp >= NN) return;
    float c = cptr[0], sc = sqrtf(c);
    float4 v = ((const float4*)(P + (size_t)warp * HD))[lane];
    float s = warp_sum(v.x * v.x + v.y * v.y + v.z * v.z + v.w * v.w);
    float n1 = fmaxf(sqrtf(s), 1e-9f);
    float sh1 = sc * sinhf(n1 / sc) / n1;
    float sx = sh1 * v.x, sy = sh1 * v.y, sz = sh1 * v.z, sw = sh1 * v.w;
    float ssum = warp_sum(sx * sx + sy * sy + sz * sz + sw * sw);
    float x0 = sqrtf(c + ssum);
    float yn = fmaxf(sqrtf(ssum), 1e-9f);
    float d = sc * acoshf(fmaxf(x0 / sc, 1.f + EPSF));
    float cf = d / yn;
    float tx = tanhf(cf * sx), ty = tanhf(cf * sy), tz = tanhf(cf * sz), tw = tanhf(cf * sw);
    float s2 = warp_sum(tx * tx + ty * ty + tz * tz + tw * tw);
    float n2 = fmaxf(sqrtf(s2), 1e-9f);
    float sh2 = sc * sinhf(n2 / sc) / n2;
    float wprev = __shfl_up_sync(0xffffffffu, tw, 1);
    float4 o;
    o.x = (lane == 0) ? sc * coshf(n2 / sc) : sh2 * wprev;
    o.y = sh2 * tx; o.z = sh2 * ty; o.w = sh2 * tz;
    ((float4*)(H + (size_t)warp * HD))[lane] = o;
}

// pooled[batch[n], loff + i] += logmap0(h[n])[i]
__global__ void pool_kernel(const float* __restrict__ H, const int* __restrict__ batch,
                            const float* __restrict__ cptr, float* __restrict__ out, int loff) {
    int warp = (blockIdx.x * blockDim.x + threadIdx.x) >> 5;
    int lane = threadIdx.x & 31;
    if (warp >= NN) return;
    float c = cptr[0], sc = sqrtf(c);
    float4 v = ((const float4*)(H + (size_t)warp * HD))[lane];
    float x0 = __shfl_sync(0xffffffffu, v.x, 0);
    float p = warp_sum(((lane == 0) ? 0.f : v.x * v.x) + v.y * v.y + v.z * v.z + v.w * v.w);
    float yn = fmaxf(sqrtf(p), 1e-9f);
    float d = sc * acoshf(fmaxf(x0 / sc, 1.f + EPSF));
    float a = d / yn;
    int g = batch[warp];
    red_v4(out + (size_t)g * (2 * HD) + loff + lane * 4,
           (lane == 0) ? 0.f : a * v.x, a * v.y, a * v.z, a * v.w);
}

// ---------------- host launcher ----------------
extern "C" void kernel_launch(void* const* d_in, const int* in_sizes, int n_in,
                              void* d_out, int out_size) {
    (void)in_sizes; (void)n_in; (void)out_size;
    const float* x     = (const float*)d_in[0];
    const float* c     = (const float*)d_in[1];
    const float* w_in  = (const float*)d_in[2];
    const float* att_w = (const float*)d_in[3];
    const float* att_b = (const float*)d_in[4];
    const float* eps   = (const float*)d_in[5];
    const float* mlp_w = (const float*)d_in[6];
    const float* mlp_b = (const float*)d_in[7];
    const int*   ei    = (const int*)d_in[8];
    const int*   batch = (const int*)d_in[9];
    float* out = (float*)d_out;

    float *ph, *pu, *pp, *phl, *pm, *pwt, *pwtin;
    int* pcnt;
    cudaGetSymbolAddress((void**)&ph, g_h);
    cudaGetSymbolAddress((void**)&pu, g_u);
    cudaGetSymbolAddress((void**)&pp, g_p);
    cudaGetSymbolAddress((void**)&phl, g_hl);
    cudaGetSymbolAddress((void**)&pm, g_m);
    cudaGetSymbolAddress((void**)&pwt, g_wt);
    cudaGetSymbolAddress((void**)&pwtin, g_wtin);
    cudaGetSymbolAddress((void**)&pcnt, g_cnt);

    static bool attr_set = false;
    if (!attr_set) {
        cudaFuncSetAttribute(gemm_kernel<IN_DIM, false>,
                             cudaFuncAttributeMaxDynamicSharedMemorySize, IN_DIM * 32 * 8);
        cudaFuncSetAttribute(gemm_kernel<HD, true>,
                             cudaFuncAttributeMaxDynamicSharedMemorySize, HD * 32 * 8);
        attr_set = true;
    }

    const int NB = (NN + 7) / 8;       // warp-per-node blocks (256 threads = 8 warps)
    const int GB = (NN + 31) / 32;     // GEMM blocks (TM=32)
    const int SM200 = IN_DIM * 32 * 8; // dynamic smem bytes
    const int SM128 = HD * 32 * 8;

    zero4_kernel<<<(GG * 2 * HD / 4 + 255) / 256, 256>>>((float4*)out, GG * 2 * HD / 4);
    prep_weights<<<(6 * HD * HD + 255) / 256, 256>>>(att_w, mlp_w);
    prep_win<<<(IN_DIM * HD + 255) / 256, 256>>>(w_in);

    // CSR build (once; reused by both layers)
    zeroi_kernel<<<(NN + 255) / 256, 256>>>(pcnt, NN);
    hist_kernel<<<(EE + 255) / 256, 256>>>(ei);
    scan_kernel<<<1, 1024>>>();
    scatter_kernel<<<(EE + 255) / 256, 256>>>(ei);

    gemm_kernel<IN_DIM, false><<<GB, 256, SM200>>>(x, pwtin, nullptr, pp);
    expmap_kernel<<<NB, 256>>>(pp, ph, c);

    for (int l = 0; l < 2; l++) {
        // attention linear -> hl
        lognode_kernel<<<NB, 256>>>(ph, pu, c);
        gemm_kernel<HD, true><<<GB, 256, SM128>>>(pu, pwt + l * HD * HD, att_b + l * DD, pp);
        expmap_kernel<<<NB, 256>>>(pp, phl, c);
        // centroid aggregation (CSR, no atomics)
        agg_kernel<<<NB, 256>>>(phl, ph, pm, c);
        combine_kernel<<<NB, 256>>>(pm, ph, c, eps, l);
        // MLP (2 hyp_linear+hyp_act)
        for (int m = 0; m < 2; m++) {
            lognode_kernel<<<NB, 256>>>(ph, pu, c);
            gemm_kernel<HD, true><<<GB, 256, SM128>>>(pu, pwt + (2 + l * 2 + m) * HD * HD,
                                                      mlp_b + (l * 2 + m) * DD, pp);
            mlp_epi_kernel<<<NB, 256>>>(pp, ph, c);
        }
        // pooled readout for this layer
        pool_kernel<<<NB, 256>>>(ph, batch, c, out, l * HD);
    }
}

// round 6
// speedup vs baseline: 1.3455x; 1.3455x over previous
#include <cuda_runtime.h>
#include <math.h>

#define NN 50000
#define EE 800000
#define IN_DIM 200
#define HD 128
#define DD 127
#define GG 512
#define EPSF 1e-5f

// ---------------- scratch (device globals; no allocation allowed) ----------------
__device__ float g_h[NN * HD];
__device__ float g_u[NN * HD];
__device__ float g_p[NN * HD];
__device__ float g_hl[NN * HD];
__device__ float g_m[NN * HD];
__device__ float g_wt[6 * HD * HD];
__device__ float g_wtin[IN_DIM * HD];
__device__ int   g_cnt[NN];         // per-node degree histogram
__device__ int   g_rowptr[NN + 1];  // CSR row pointers
__device__ int   g_cur[NN];         // scatter cursors
__device__ int   g_dstidx[EE];      // CSR dst indices
__device__ int   g_blksum[256];     // block sums for decoupled scan
__device__ int   g_blkoff[256];     // block offsets

__device__ __forceinline__ float warp_sum(float v) {
#pragma unroll
    for (int o = 16; o; o >>= 1) v += __shfl_xor_sync(0xffffffffu, v, o);
    return v;
}

__device__ __forceinline__ void red_v4(float* p, float a, float b, float c, float d) {
    asm volatile("red.global.add.v4.f32 [%0], {%1,%2,%3,%4};"
                 :: "l"(p), "f"(a), "f"(b), "f"(c), "f"(d) : "memory");
}

// ---------------- utility kernels ----------------
__global__ void zero4_kernel(float4* __restrict__ p, int n4) {
    int i = blockIdx.x * blockDim.x + threadIdx.x;
    if (i < n4) p[i] = make_float4(0.f, 0.f, 0.f, 0.f);
}

__global__ void zeroi_kernel(int* __restrict__ p, int n) {
    int i = blockIdx.x * blockDim.x + threadIdx.x;
    if (i < n) p[i] = 0;
}

__global__ void prep_weights(const float* __restrict__ att_w, const float* __restrict__ mlp_w) {
    int idx = blockIdx.x * blockDim.x + threadIdx.x;
    if (idx >= 6 * HD * HD) return;
    int w = idx >> 14;
    int k = (idx >> 7) & 127;
    int j = idx & 127;
    float val = 0.f;
    if (k < DD && j < DD) {
        const float* src = (w < 2) ? (att_w + w * DD * DD) : (mlp_w + (w - 2) * DD * DD);
        val = src[j * DD + k];
    }
    g_wt[idx] = val;
}

__global__ void prep_win(const float* __restrict__ w_in) {
    int idx = blockIdx.x * blockDim.x + threadIdx.x;
    if (idx >= IN_DIM * HD) return;
    int k = idx >> 7;
    int j = idx & 127;
    g_wtin[idx] = (j < DD) ? w_in[k * DD + j] : 0.f;
}

// ---------------- CSR build (hist + decoupled 3-phase scan + scatter) ----------------
__global__ void hist_kernel(const int* __restrict__ ei) {
    int e = blockIdx.x * blockDim.x + threadIdx.x;
    if (e < EE) atomicAdd(&g_cnt[ei[e]], 1);
}

// phase 1: per-block inclusive scan of 256 counts; write in-block exclusive to rowptr
__global__ void scan1_kernel() {
    __shared__ int sh[256];
    int t = threadIdx.x;
    int idx = blockIdx.x * 256 + t;
    int v = (idx < NN) ? g_cnt[idx] : 0;
    sh[t] = v;
    __syncthreads();
#pragma unroll
    for (int d = 1; d < 256; d <<= 1) {
        int o = (t >= d) ? sh[t - d] : 0;
        __syncthreads();
        sh[t] += o;
        __syncthreads();
    }
    if (idx < NN) g_rowptr[idx] = sh[t] - v;
    if (t == 255) g_blksum[blockIdx.x] = sh[255];
}

// phase 2: scan block sums (NBLK <= 256) in one block
__global__ void scan2_kernel(int nblk) {
    __shared__ int sh[256];
    int t = threadIdx.x;
    int v = (t < nblk) ? g_blksum[t] : 0;
    sh[t] = v;
    __syncthreads();
#pragma unroll
    for (int d = 1; d < 256; d <<= 1) {
        int o = (t >= d) ? sh[t - d] : 0;
        __syncthreads();
        sh[t] += o;
        __syncthreads();
    }
    if (t < nblk) g_blkoff[t] = sh[t] - v;
    if (t == 255) g_rowptr[NN] = sh[255];   // total = EE
}

// phase 3: add block offset, init cursors
__global__ void scan3_kernel() {
    int idx = blockIdx.x * 256 + threadIdx.x;
    if (idx >= NN) return;
    int r = g_rowptr[idx] + g_blkoff[blockIdx.x];
    g_rowptr[idx] = r;
    g_cur[idx] = r;
}

__global__ void scatter_kernel(const int* __restrict__ ei) {
    int e = blockIdx.x * blockDim.x + threadIdx.x;
    if (e >= EE) return;
    int s = ei[e];
    int pos = atomicAdd(&g_cur[s], 1);
    g_dstidx[pos] = ei[EE + e];
}

// ---------------- GEMM: P[n][j] = sum_k U[n][k] * WT[k][j] (+ bias) ----------------
// (R3 version — measured at 97% of the scalar-FFMA issue ceiling)
template <int K, bool HASBIAS>
__global__ void __launch_bounds__(256) gemm_kernel(const float* __restrict__ U,
                                                   const float* __restrict__ WT,
                                                   const float* __restrict__ bias,
                                                   float* __restrict__ P) {
    constexpr int TM = (K > 128) ? 56 : 64;   // keep static smem under 48KB
    constexpr int RPT = TM / 8;
    constexpr int K4 = K / 4;
    __shared__ __align__(16) float4 xs[TM * K4];
    int tid = threadIdx.x;
    int cg = tid & 31;          // column group: cols 4*cg .. 4*cg+3
    int rg = tid >> 5;          // row group: rows rg*RPT .. rg*RPT+RPT-1
    int row0 = blockIdx.x * TM;

    for (int i = tid; i < TM * K4; i += 256) {
        int m = i / K4, k4 = i - m * K4;
        int r = row0 + m;
        xs[i] = (r < NN) ? ((const float4*)(U + (size_t)r * K))[k4]
                         : make_float4(0.f, 0.f, 0.f, 0.f);
    }
    __syncthreads();

    float acc[RPT][4];
#pragma unroll
    for (int r = 0; r < RPT; r++) {
        acc[r][0] = 0.f; acc[r][1] = 0.f; acc[r][2] = 0.f; acc[r][3] = 0.f;
    }

    const float4* W4 = (const float4*)WT;
#pragma unroll 4
    for (int kq = 0; kq < K4; kq++) {
        float4 w0 = W4[(kq * 4 + 0) * 32 + cg];
        float4 w1 = W4[(kq * 4 + 1) * 32 + cg];
        float4 w2 = W4[(kq * 4 + 2) * 32 + cg];
        float4 w3 = W4[(kq * 4 + 3) * 32 + cg];
#pragma unroll
        for (int r = 0; r < RPT; r++) {
            float4 xv = xs[(rg * RPT + r) * K4 + kq];
            acc[r][0] = fmaf(xv.x, w0.x, acc[r][0]);
            acc[r][1] = fmaf(xv.x, w0.y, acc[r][1]);
            acc[r][2] = fmaf(xv.x, w0.z, acc[r][2]);
            acc[r][3] = fmaf(xv.x, w0.w, acc[r][3]);
            acc[r][0] = fmaf(xv.y, w1.x, acc[r][0]);
            acc[r][1] = fmaf(xv.y, w1.y, acc[r][1]);
            acc[r][2] = fmaf(xv.y, w1.z, acc[r][2]);
            acc[r][3] = fmaf(xv.y, w1.w, acc[r][3]);
            acc[r][0] = fmaf(xv.z, w2.x, acc[r][0]);
            acc[r][1] = fmaf(xv.z, w2.y, acc[r][1]);
            acc[r][2] = fmaf(xv.z, w2.z, acc[r][2]);
            acc[r][3] = fmaf(xv.z, w2.w, acc[r][3]);
            acc[r][0] = fmaf(xv.w, w3.x, acc[r][0]);
            acc[r][1] = fmaf(xv.w, w3.y, acc[r][1]);
            acc[r][2] = fmaf(xv.w, w3.z, acc[r][2]);
            acc[r][3] = fmaf(xv.w, w3.w, acc[r][3]);
        }
    }

    float4 bv = make_float4(0.f, 0.f, 0.f, 0.f);
    if (HASBIAS) {
        int j0 = 4 * cg;
        bv.x = (j0 + 0 < DD) ? bias[j0 + 0] : 0.f;
        bv.y = (j0 + 1 < DD) ? bias[j0 + 1] : 0.f;
        bv.z = (j0 + 2 < DD) ? bias[j0 + 2] : 0.f;
        bv.w = (j0 + 3 < DD) ? bias[j0 + 3] : 0.f;
    }
#pragma unroll
    for (int r = 0; r < RPT; r++) {
        int gr = row0 + rg * RPT + r;
        if (gr < NN) {
            float4 res;
            res.x = acc[r][0] + bv.x;
            res.y = acc[r][1] + bv.y;
            res.z = acc[r][2] + bv.z;
            res.w = (cg == 31) ? 0.f : acc[r][3] + bv.w;  // col 127 is padding
            ((float4*)(P + (size_t)gr * HD))[cg] = res;
        }
    }
}

// ---------------- warp-per-node elementwise kernels ----------------

// out = proj(expmap0([0, P]))
__global__ void expmap_kernel(const float* __restrict__ P, float* __restrict__ out,
                              const float* __restrict__ cptr) {
    int warp = (blockIdx.x * blockDim.x + threadIdx.x) >> 5;
    int lane = threadIdx.x & 31;
    if (warp >= NN) return;
    float c = cptr[0], sc = sqrtf(c);
    float4 v = ((const float4*)(P + (size_t)warp * HD))[lane];
    float s = warp_sum(v.x * v.x + v.y * v.y + v.z * v.z + v.w * v.w);
    float n = fmaxf(sqrtf(s), 1e-9f);
    float sh = sc * sinhf(n / sc) / n;
    float wprev = __shfl_up_sync(0xffffffffu, v.w, 1);
    float4 o;
    o.x = (lane == 0) ? 0.f : sh * wprev;
    o.y = sh * v.x; o.z = sh * v.y; o.w = sh * v.z;
    float ss = warp_sum(((lane == 0) ? 0.f : o.x * o.x) + o.y * o.y + o.z * o.z + o.w * o.w);
    if (lane == 0) o.x = sqrtf(c + ss);
    ((float4*)(out + (size_t)warp * HD))[lane] = o;
}

// U = logmap0(H) spatial
__global__ void lognode_kernel(const float* __restrict__ H, float* __restrict__ U,
                               const float* __restrict__ cptr) {
    int warp = (blockIdx.x * blockDim.x + threadIdx.x) >> 5;
    int lane = threadIdx.x & 31;
    if (warp >= NN) return;
    float c = cptr[0], sc = sqrtf(c);
    float4 v = ((const float4*)(H + (size_t)warp * HD))[lane];
    float x0 = __shfl_sync(0xffffffffu, v.x, 0);
    float px = (lane == 0) ? 0.f : v.x * v.x;
    float s = warp_sum(px + v.y * v.y + v.z * v.z + v.w * v.w);
    float yn = fmaxf(sqrtf(s), 1e-9f);
    float d = sc * acoshf(fmaxf(x0 / sc, 1.f + EPSF));
    float a = d / yn;
    float nx = __shfl_down_sync(0xffffffffu, v.x, 1);
    float4 o;
    o.x = a * v.y; o.y = a * v.z; o.z = a * v.w;
    o.w = (lane == 31) ? 0.f : a * nx;
    ((float4*)(U + (size_t)warp * HD))[lane] = o;
}

// warp per SRC node over CSR: m[s] = sum_{e in row s} exp(-dist(hl[s],hl[d])) * h[d]
// register accumulation, plain store — no zeroing, no atomics, hl[s] loaded once.
__global__ void agg_kernel(const float* __restrict__ hl, const float* __restrict__ h,
                           float* __restrict__ m, const float* __restrict__ cptr) {
    int warp = (blockIdx.x * blockDim.x + threadIdx.x) >> 5;
    int lane = threadIdx.x & 31;
    if (warp >= NN) return;
    float c = cptr[0], sc = sqrtf(c);
    int beg = g_rowptr[warp], end = g_rowptr[warp + 1];
    float4 a = ((const float4*)(hl + (size_t)warp * HD))[lane];
    float4 acc = make_float4(0.f, 0.f, 0.f, 0.f);
    int d = (beg < end) ? g_dstidx[beg] : 0;
    for (int e = beg; e < end; e++) {
        int dn = (e + 1 < end) ? g_dstidx[e + 1] : 0;  // prefetch next index
        float4 b = ((const float4*)(hl + (size_t)d * HD))[lane];
        float4 hv = ((const float4*)(h + (size_t)d * HD))[lane];
        float p = ((lane == 0) ? -a.x * b.x : a.x * b.x) + a.y * b.y + a.z * b.z + a.w * b.w;
        p = warp_sum(p);
        float val = fmaxf(-p / c, 1.f + EPSF);
        float att = expf(-sc * acoshf(val));
        acc.x = fmaf(att, hv.x, acc.x);
        acc.y = fmaf(att, hv.y, acc.y);
        acc.z = fmaf(att, hv.z, acc.z);
        acc.w = fmaf(att, hv.w, acc.w);
        d = dn;
    }
    ((float4*)(m + (size_t)warp * HD))[lane] = acc;
}

// GIN combine
__global__ void combine_kernel(const float* __restrict__ Mv, float* __restrict__ H,
                               const float* __restrict__ cptr, const float* __restrict__ epsp,
                               int l) {
    int warp = (blockIdx.x * blockDim.x + threadIdx.x) >> 5;
    int lane = threadIdx.x & 31;
    if (warp >= NN) return;
    float c = cptr[0], sc = sqrtf(c), ep = epsp[l];
    float4 mv = ((const float4*)(Mv + (size_t)warp * HD))[lane];
    float4 hv = ((const float4*)(H + (size_t)warp * HD))[lane];
    float m0 = __shfl_sync(0xffffffffu, mv.x, 0);
    float pm = warp_sum(((lane == 0) ? 0.f : mv.x * mv.x) + mv.y * mv.y + mv.z * mv.z + mv.w * mv.w);
    float denom = sqrtf(fmaxf(m0 * m0 - pm, 1e-9f));
    float r = sc / denom;
    float ax = r * mv.x, ay = r * mv.y, az = r * mv.z, aw = r * mv.w;
    float ssum = warp_sum(((lane == 0) ? 0.f : ax * ax) + ay * ay + az * az + aw * aw);
    float t = sqrtf(c + ssum);
    float yn_a = fmaxf(sqrtf(ssum), 1e-9f);
    float d1 = sc * acoshf(fmaxf(t / sc, 1.f + EPSF));
    float cA = d1 / yn_a;
    float ph = warp_sum(((lane == 0) ? 0.f : hv.x * hv.x) + hv.y * hv.y + hv.z * hv.z + hv.w * hv.w);
    float hp0 = sqrtf(c + ph);
    float yn_h = fmaxf(sqrtf(ph), 1e-9f);
    float d2 = sc * acoshf(fmaxf(hp0 / sc, 1.f + EPSF));
    float cH = (1.f + ep) * d2 / yn_h;
    float4 vv;
    vv.x = (lane == 0) ? 0.f : cA * ax + cH * hv.x;
    vv.y = cA * ay + cH * hv.y;
    vv.z = cA * az + cH * hv.z;
    vv.w = cA * aw + cH * hv.w;
    float pv = warp_sum(vv.x * vv.x + vv.y * vv.y + vv.z * vv.z + vv.w * vv.w);
    float n = fmaxf(sqrtf(pv), 1e-9f);
    float sh = sc * sinhf(n / sc) / n;
    float4 o;
    o.x = (lane == 0) ? 0.f : sh * vv.x;
    o.y = sh * vv.y; o.z = sh * vv.z; o.w = sh * vv.w;
    float so = warp_sum(((lane == 0) ? 0.f : o.x * o.x) + o.y * o.y + o.z * o.z + o.w * o.w);
    if (lane == 0) o.x = sqrtf(c + so);
    ((float4*)(H + (size_t)warp * HD))[lane] = o;
}

// MLP epilogue: H = hyp_act(proj(expmap0([0,P])))
__global__ void mlp_epi_kernel(const float* __restrict__ P, float* __restrict__ H,
                               const float* __restrict__ cptr) {
    int warp = (blockIdx.x * blockDim.x + threadIdx.x) >> 5;
    int lane = threadIdx.x & 31;
    if (warp >= NN) return;
    float c = cptr[0], sc = sqrtf(c);
    float4 v = ((const float4*)(P + (size_t)warp * HD))[lane];
    float s = warp_sum(v.x * v.x + v.y * v.y + v.z * v.z + v.w * v.w);
    float n1 = fmaxf(sqrtf(s), 1e-9f);
    float sh1 = sc * sinhf(n1 / sc) / n1;
    float sx = sh1 * v.x, sy = sh1 * v.y, sz = sh1 * v.z, sw = sh1 * v.w;
    float ssum = warp_sum(sx * sx + sy * sy + sz * sz + sw * sw);
    float x0 = sqrtf(c + ssum);
    float yn = fmaxf(sqrtf(ssum), 1e-9f);
    float d = sc * acoshf(fmaxf(x0 / sc, 1.f + EPSF));
    float cf = d / yn;
    float tx = tanhf(cf * sx), ty = tanhf(cf * sy), tz = tanhf(cf * sz), tw = tanhf(cf * sw);
    float s2 = warp_sum(tx * tx + ty * ty + tz * tz + tw * tw);
    float n2 = fmaxf(sqrtf(s2), 1e-9f);
    float sh2 = sc * sinhf(n2 / sc) / n2;
    float wprev = __shfl_up_sync(0xffffffffu, tw, 1);
    float4 o;
    o.x = (lane == 0) ? sc * coshf(n2 / sc) : sh2 * wprev;
    o.y = sh2 * tx; o.z = sh2 * ty; o.w = sh2 * tz;
    ((float4*)(H + (size_t)warp * HD))[lane] = o;
}

// pooled[batch[n], loff + i] += logmap0(h[n])[i]
__global__ void pool_kernel(const float* __restrict__ H, const int* __restrict__ batch,
                            const float* __restrict__ cptr, float* __restrict__ out, int loff) {
    int warp = (blockIdx.x * blockDim.x + threadIdx.x) >> 5;
    int lane = threadIdx.x & 31;
    if (warp >= NN) return;
    float c = cptr[0], sc = sqrtf(c);
    float4 v = ((const float4*)(H + (size_t)warp * HD))[lane];
    float x0 = __shfl_sync(0xffffffffu, v.x, 0);
    float p = warp_sum(((lane == 0) ? 0.f : v.x * v.x) + v.y * v.y + v.z * v.z + v.w * v.w);
    float yn = fmaxf(sqrtf(p), 1e-9f);
    float d = sc * acoshf(fmaxf(x0 / sc, 1.f + EPSF));
    float a = d / yn;
    int g = batch[warp];
    red_v4(out + (size_t)g * (2 * HD) + loff + lane * 4,
           (lane == 0) ? 0.f : a * v.x, a * v.y, a * v.z, a * v.w);
}

// ---------------- host launcher ----------------
extern "C" void kernel_launch(void* const* d_in, const int* in_sizes, int n_in,
                              void* d_out, int out_size) {
    (void)in_sizes; (void)n_in; (void)out_size;
    const float* x     = (const float*)d_in[0];
    const float* c     = (const float*)d_in[1];
    const float* w_in  = (const float*)d_in[2];
    const float* att_w = (const float*)d_in[3];
    const float* att_b = (const float*)d_in[4];
    const float* eps   = (const float*)d_in[5];
    const float* mlp_w = (const float*)d_in[6];
    const float* mlp_b = (const float*)d_in[7];
    const int*   ei    = (const int*)d_in[8];
    const int*   batch = (const int*)d_in[9];
    float* out = (float*)d_out;

    float *ph, *pu, *pp, *phl, *pm, *pwt, *pwtin;
    int* pcnt;
    cudaGetSymbolAddress((void**)&ph, g_h);
    cudaGetSymbolAddress((void**)&pu, g_u);
    cudaGetSymbolAddress((void**)&pp, g_p);
    cudaGetSymbolAddress((void**)&phl, g_hl);
    cudaGetSymbolAddress((void**)&pm, g_m);
    cudaGetSymbolAddress((void**)&pwt, g_wt);
    cudaGetSymbolAddress((void**)&pwtin, g_wtin);
    cudaGetSymbolAddress((void**)&pcnt, g_cnt);

    const int NB = (NN + 7) / 8;        // warp-per-node blocks (256 threads = 8 warps)
    const int GB200 = (NN + 55) / 56;   // GEMM K=200 blocks (TM=56)
    const int GB128 = (NN + 63) / 64;   // GEMM K=128 blocks (TM=64)
    const int SCB = (NN + 255) / 256;   // scan blocks (196)

    zero4_kernel<<<(GG * 2 * HD / 4 + 255) / 256, 256>>>((float4*)out, GG * 2 * HD / 4);
    prep_weights<<<(6 * HD * HD + 255) / 256, 256>>>(att_w, mlp_w);
    prep_win<<<(IN_DIM * HD + 255) / 256, 256>>>(w_in);

    // CSR build (once; reused by both layers)
    zeroi_kernel<<<SCB, 256>>>(pcnt, NN);
    hist_kernel<<<(EE + 255) / 256, 256>>>(ei);
    scan1_kernel<<<SCB, 256>>>();
    scan2_kernel<<<1, 256>>>(SCB);
    scan3_kernel<<<SCB, 256>>>();
    scatter_kernel<<<(EE + 255) / 256, 256>>>(ei);

    gemm_kernel<IN_DIM, false><<<GB200, 256>>>(x, pwtin, nullptr, pp);
    expmap_kernel<<<NB, 256>>>(pp, ph, c);

    for (int l = 0; l < 2; l++) {
        // attention linear -> hl
        lognode_kernel<<<NB, 256>>>(ph, pu, c);
        gemm_kernel<HD, true><<<GB128, 256>>>(pu, pwt + l * HD * HD, att_b + l * DD, pp);
        expmap_kernel<<<NB, 256>>>(pp, phl, c);
        // centroid aggregation (CSR, no atomics, no zeroing)
        agg_kernel<<<NB, 256>>>(phl, ph, pm, c);
        combine_kernel<<<NB, 256>>>(pm, ph, c, eps, l);
        // MLP (2 hyp_linear+hyp_act)
        for (int m = 0; m < 2; m++) {
            lognode_kernel<<<NB, 256>>>(ph, pu, c);
            gemm_kernel<HD, true><<<GB128, 256>>>(pu, pwt + (2 + l * 2 + m) * HD * HD,
                                                  mlp_b + (l * 2 + m) * DD, pp);
            mlp_epi_kernel<<<NB, 256>>>(pp, ph, c);
        }
        // pooled readout for this layer
        pool_kernel<<<NB, 256>>>(ph, batch, c, out, l * HD);
    }
}